// round 15
// baseline (speedup 1.0000x reference)
#include <cuda_runtime.h>
#include <math.h>
#include <float.h>

#define BATCH 2
#define NP    32768
#define NLEV  4
#define NSLOTV 8           // (level, batch) voxel slots
#define NSLOTT 10          // + 2 point slots (one per batch)
#define PB    256          // stats partial chunks per batch
#define MAXC  256
#define CHUNK 512          // cells per scan chunk
#define MAXCHUNK 320
#define MARGIN 0.0625f     // screening margin (>> fp32 err of s-form @ scene 50m)

// ---------------- static device scratch (no allocations allowed) ------------
__device__ unsigned g_bb  [NSLOTT * 6];     // encoded bbox: min x,y,z / max x,y,z
__device__ int      g_cnt [150000];
__device__ int      g_off [150016];         // +1 sentinel per slot
__device__ int      g_fill[150000];
__device__ int      g_bsum[MAXCHUNK];
__device__ int      g_boff[MAXCHUNK];
__device__ float4   g_svox[184320];         // binned {x,y,z, h=0.5|v|^2}
__device__ int      g_sidx[184320];         // binned original indices
__device__ int      g_pid [BATCH * NP];     // sorted position -> original point idx
__device__ int      g_idx [NLEV * BATCH * NP * 3];   // indexed by SORTED position
__device__ float    g_w   [NLEV * BATCH * NP * 3];   // indexed by SORTED position
__device__ float    g_psum[NLEV * BATCH * PB * MAXC];
__device__ float    g_psqs[NLEV * BATCH * PB * MAXC];
__device__ float    g_mu  [NLEV * BATCH * MAXC];
__device__ float    g_rstd[NLEV * BATCH * MAXC];

struct GridParams {
    const float* vc[NSLOTT];
    int nv[NSLOTT];
    int gs[NSLOTT];
    int cellbase[NSLOTT];
    int offbase[NSLOTT];
    int svbase[NSLOTT];
};
struct ScanParams { int cstart[NSLOTT + 1]; };  // chunk-index boundaries per slot
struct EpiParams {
    const float* vf[NLEV];
    const float* gamma[NLEV];
    const float* beta[NLEV];
    float* outp[NLEV];
    int C[NLEV];
    int Nv[NLEV];
};

// order-preserving float <-> uint for atomicMin/Max
__device__ __forceinline__ unsigned fenc(float f) {
    unsigned u = __float_as_uint(f);
    return (u & 0x80000000u) ? ~u : (u | 0x80000000u);
}
__device__ __forceinline__ float fdec(unsigned u) {
    unsigned v = (u & 0x80000000u) ? (u & 0x7FFFFFFFu) : ~u;
    return __uint_as_float(v);
}
__device__ __forceinline__ int clampi(int v, int lo, int hi) {
    return v < lo ? lo : (v > hi ? hi : v);
}
__device__ __forceinline__ int chunk_slot(int ch, const ScanParams& sp) {
    int s = 0;
    #pragma unroll
    for (int i = 1; i < NSLOTT; i++) if (ch >= sp.cstart[i]) s = i;
    return s;
}

// Morton (Z-order) interleave
__device__ __forceinline__ unsigned part1by2(unsigned v) {
    v &= 0x3FF;
    v = (v | (v << 16)) & 0x030000FF;
    v = (v | (v <<  8)) & 0x0300F00F;
    v = (v | (v <<  4)) & 0x030C30C3;
    v = (v | (v <<  2)) & 0x09249249;
    return v;
}
// row-major for voxel slots (row-merged scans), Morton for point slots
__device__ __forceinline__ int cell_index(int s, int gs, int cx, int cy, int cz) {
    if (s < NSLOTV) return (cz * gs + cy) * gs + cx;
    return (int)(part1by2((unsigned)cx) | (part1by2((unsigned)cy) << 1)
               | (part1by2((unsigned)cz) << 2));
}

// ---------------- init ------------------------------------------------------
__global__ void init_kernel(int totcells) {
    int i = blockIdx.x * blockDim.x + threadIdx.x;
    if (i < totcells) { g_cnt[i] = 0; g_fill[i] = 0; }
    if (i < NSLOTT * 6) g_bb[i] = (i % 6 < 3) ? 0xFFFFFFFFu : 0u;
}

// ---------------- per-slot bbox ---------------------------------------------
__global__ void bbox_kernel(GridParams gp) {
    int s = blockIdx.y;
    int nv = gp.nv[s];
    int i = blockIdx.x * 256 + threadIdx.x;
    float x = FLT_MAX, y = FLT_MAX, z = FLT_MAX;
    float X = -FLT_MAX, Y = -FLT_MAX, Z = -FLT_MAX;
    if (i < nv) {
        const float* v = gp.vc[s] + (size_t)i * 3;
        x = X = v[0]; y = Y = v[1]; z = Z = v[2];
    }
    #pragma unroll
    for (int d = 16; d; d >>= 1) {
        x = fminf(x, __shfl_xor_sync(0xFFFFFFFFu, x, d));
        y = fminf(y, __shfl_xor_sync(0xFFFFFFFFu, y, d));
        z = fminf(z, __shfl_xor_sync(0xFFFFFFFFu, z, d));
        X = fmaxf(X, __shfl_xor_sync(0xFFFFFFFFu, X, d));
        Y = fmaxf(Y, __shfl_xor_sync(0xFFFFFFFFu, Y, d));
        Z = fmaxf(Z, __shfl_xor_sync(0xFFFFFFFFu, Z, d));
    }
    if ((threadIdx.x & 31) == 0) {
        atomicMin(&g_bb[s * 6 + 0], fenc(x));
        atomicMin(&g_bb[s * 6 + 1], fenc(y));
        atomicMin(&g_bb[s * 6 + 2], fenc(z));
        atomicMax(&g_bb[s * 6 + 3], fenc(X));
        atomicMax(&g_bb[s * 6 + 4], fenc(Y));
        atomicMax(&g_bb[s * 6 + 5], fenc(Z));
    }
}

// identical cell computation used by count / scatter / query
__device__ __forceinline__ void load_grid(int s, int gs,
    float& bx0, float& by0, float& bz0, float& sx, float& sy, float& sz) {
    bx0 = fdec(g_bb[s * 6 + 0]); by0 = fdec(g_bb[s * 6 + 1]); bz0 = fdec(g_bb[s * 6 + 2]);
    float bx1 = fdec(g_bb[s * 6 + 3]), by1 = fdec(g_bb[s * 6 + 4]), bz1 = fdec(g_bb[s * 6 + 5]);
    sx = gs / fmaxf(bx1 - bx0, 1e-9f);
    sy = gs / fmaxf(by1 - by0, 1e-9f);
    sz = gs / fmaxf(bz1 - bz0, 1e-9f);
}

// ---------------- count -----------------------------------------------------
__global__ void count_kernel(GridParams gp) {
    int s = blockIdx.y;
    int nv = gp.nv[s];
    int i = blockIdx.x * 256 + threadIdx.x;
    if (i >= nv) return;
    int gs = gp.gs[s];
    float bx0, by0, bz0, sx, sy, sz;
    load_grid(s, gs, bx0, by0, bz0, sx, sy, sz);
    const float* v = gp.vc[s] + (size_t)i * 3;
    int cx = clampi((int)((v[0] - bx0) * sx), 0, gs - 1);
    int cy = clampi((int)((v[1] - by0) * sy), 0, gs - 1);
    int cz = clampi((int)((v[2] - bz0) * sz), 0, gs - 1);
    atomicAdd(&g_cnt[gp.cellbase[s] + cell_index(s, gs, cx, cy, cz)], 1);
}

// ---------------- 3-phase scan (cell regions padded to CHUNK multiples) ------
__global__ __launch_bounds__(CHUNK) void scan1_kernel(GridParams gp, ScanParams sp) {
    __shared__ int ws[16];
    const int ch = blockIdx.x, t = threadIdx.x;
    const int s = chunk_slot(ch, sp);
    const int local = (ch - sp.cstart[s]) * CHUNK + t;
    const int lane = t & 31, wid = t >> 5;

    int v = g_cnt[gp.cellbase[s] + local];
    int sv = v;
    #pragma unroll
    for (int d = 1; d < 32; d <<= 1) {
        int o = __shfl_up_sync(0xFFFFFFFFu, sv, d);
        if (lane >= d) sv += o;
    }
    if (lane == 31) ws[wid] = sv;
    __syncthreads();
    if (wid == 0) {
        int w = (lane < 16) ? ws[lane] : 0;
        #pragma unroll
        for (int d = 1; d < 16; d <<= 1) {
            int o = __shfl_up_sync(0xFFFFFFFFu, w, d);
            if (lane >= d) w += o;
        }
        if (lane < 16) ws[lane] = w;
    }
    __syncthreads();
    int excl = sv - v + (wid ? ws[wid - 1] : 0);
    g_off[gp.offbase[s] + local] = excl;
    if (t == CHUNK - 1) g_bsum[ch] = excl + v;
}

__global__ void scan2_kernel(GridParams gp, ScanParams sp) {
    const int w = threadIdx.x >> 5;       // slot
    const int lane = threadIdx.x & 31;
    const int c0 = sp.cstart[w], c1 = sp.cstart[w + 1];
    int running = 0;
    for (int base = c0; base < c1; base += 32) {
        int i = base + lane;
        int v = (i < c1) ? g_bsum[i] : 0;
        int sv = v;
        #pragma unroll
        for (int d = 1; d < 32; d <<= 1) {
            int o = __shfl_up_sync(0xFFFFFFFFu, sv, d);
            if (lane >= d) sv += o;
        }
        if (i < c1) g_boff[i] = running + sv - v;
        running += __shfl_sync(0xFFFFFFFFu, sv, 31);
    }
    if (lane == 0) {
        int n = gp.gs[w] * gp.gs[w] * gp.gs[w];
        if (n % CHUNK == 0) g_off[gp.offbase[w] + n] = running;
    }
}

__global__ __launch_bounds__(CHUNK) void scan3_kernel(GridParams gp, ScanParams sp) {
    const int ch = blockIdx.x, t = threadIdx.x;
    const int s = chunk_slot(ch, sp);
    const int local = (ch - sp.cstart[s]) * CHUNK + t;
    g_off[gp.offbase[s] + local] += g_boff[ch];
}

// ---------------- scatter (sorts; stores h = 0.5|v|^2 in .w, idx separately) --
__global__ void scatter_kernel(GridParams gp) {
    int s = blockIdx.y;
    int nv = gp.nv[s];
    int i = blockIdx.x * 256 + threadIdx.x;
    if (i >= nv) return;
    int gs = gp.gs[s];
    float bx0, by0, bz0, sx, sy, sz;
    load_grid(s, gs, bx0, by0, bz0, sx, sy, sz);
    const float* v = gp.vc[s] + (size_t)i * 3;
    float x = v[0], y = v[1], z = v[2];
    int cx = clampi((int)((x - bx0) * sx), 0, gs - 1);
    int cy = clampi((int)((y - by0) * sy), 0, gs - 1);
    int cz = clampi((int)((z - bz0) * sz), 0, gs - 1);
    int cell = cell_index(s, gs, cx, cy, cz);
    int pos = g_off[gp.offbase[s] + cell] + atomicAdd(&g_fill[gp.cellbase[s] + cell], 1);
    float h = 0.5f * fmaf(x, x, fmaf(y, y, z * z));
    g_svox[gp.svbase[s] + pos] = make_float4(x, y, z, h);
    g_sidx[gp.svbase[s] + pos] = i;
}

// ---------------- query: exact 3-NN with screened inner loop ------------------
// Screen s = h - p.v  vs  sthr = 0.5*(b2 + MARGIN - pp); exact fp32 (p-v)^2
// recompute on the rare pass path decides all insertions, so the selected
// top-3 matches the exact brute force (margin covers s-form fp error).
struct Best {
    float b0, b1, b2, pp, sthr;
    int i0, i1, i2;
};
__device__ __forceinline__ void upd_thr(Best& B) {
    B.sthr = 0.5f * (B.b2 + MARGIN - B.pp);
}
__device__ __forceinline__ void scan_range(int st, int en, int sb,
    float qx, float qy, float qz, Best& B)
{
    for (int j = st; j < en; j++) {
        float4 v = __ldg(&g_svox[sb + j]);
        float sc = fmaf(-qx, v.x, v.w);
        sc = fmaf(-qy, v.y, sc);
        sc = fmaf(-qz, v.z, sc);
        if (sc < B.sthr) {                     // rare
            float dx = qx - v.x, dy = qy - v.y, dz = qz - v.z;
            float d2 = fmaf(dx, dx, fmaf(dy, dy, dz * dz));  // exact fp32
            if (d2 < B.b2) {
                int idx = __ldg(&g_sidx[sb + j]);
                if (d2 < B.b1) {
                    B.b2 = B.b1; B.i2 = B.i1;
                    if (d2 < B.b0) { B.b1 = B.b0; B.i1 = B.i0; B.b0 = d2; B.i0 = idx; }
                    else           { B.b1 = d2;   B.i1 = idx; }
                } else { B.b2 = d2; B.i2 = idx; }
                upd_thr(B);
            }
        }
    }
}
__device__ __forceinline__ void scan_cell(int cell, int ob, int sb,
    float qx, float qy, float qz, Best& B)
{
    int st = __ldg(&g_off[ob + cell]), en = __ldg(&g_off[ob + cell + 1]);
    scan_range(st, en, sb, qx, qy, qz, B);
}

// One thread = one (batch, point, LEVEL); points in Morton-sorted order.
__global__ __launch_bounds__(256) void query_kernel(GridParams gp)
{
    int gid = blockIdx.x * 256 + threadIdx.x;   // over BATCH*NP sorted points
    int L  = blockIdx.y;
    int b  = gid >> 15;
    int i  = gid & (NP - 1);

    float4 pv = __ldg(&g_svox[gp.svbase[NSLOTV + b] + i]);
    float qx = pv.x, qy = pv.y, qz = pv.z;

    if (L == 0) g_pid[b * NP + i] = __ldg(&g_sidx[gp.svbase[NSLOTV + b] + i]);

    const int s = L * 2 + b;
    int gs = gp.gs[s];
    float bx0, by0, bz0, sx, sy, sz;
    load_grid(s, gs, bx0, by0, bz0, sx, sy, sz);
    float csx = 1.0f / sx, csy = 1.0f / sy, csz = 1.0f / sz;

    int cx = clampi((int)((qx - bx0) * sx), 0, gs - 1);
    int cy = clampi((int)((qy - by0) * sy), 0, gs - 1);
    int cz = clampi((int)((qz - bz0) * sz), 0, gs - 1);

    const int ob = gp.offbase[s];
    const int sb = gp.svbase[s];

    Best B;
    B.b0 = B.b1 = B.b2 = FLT_MAX;
    B.i0 = B.i1 = B.i2 = 0;
    B.pp = fmaf(qx, qx, fmaf(qy, qy, qz * qz));
    upd_thr(B);

    // ---- fast path: clamped 3x3x3 block, row-merged ----
    {
        int zlo = max(cz - 1, 0), zhi = min(cz + 1, gs - 1);
        int ylo = max(cy - 1, 0), yhi = min(cy + 1, gs - 1);
        int xlo = max(cx - 1, 0), xhi = min(cx + 1, gs - 1);
        for (int z = zlo; z <= zhi; z++)
            for (int y = ylo; y <= yhi; y++) {
                int rb = (z * gs + y) * gs;
                int st = __ldg(&g_off[ob + rb + xlo]);
                int en = __ldg(&g_off[ob + rb + xhi + 1]);
                scan_range(st, en, sb, qx, qy, qz, B);
            }
    }
    // clearance of the R=1 box
    bool done;
    {
        float cl = FLT_MAX;
        if (cx - 1 > 0)      cl = fminf(cl, qx - (bx0 + (cx - 1) * csx));
        if (cx + 1 < gs - 1) cl = fminf(cl, (bx0 + (cx + 2) * csx) - qx);
        if (cy - 1 > 0)      cl = fminf(cl, qy - (by0 + (cy - 1) * csy));
        if (cy + 1 < gs - 1) cl = fminf(cl, (by0 + (cy + 2) * csy) - qy);
        if (cz - 1 > 0)      cl = fminf(cl, qz - (bz0 + (cz - 1) * csz));
        if (cz + 1 < gs - 1) cl = fminf(cl, (bz0 + (cz + 2) * csz) - qz);
        cl -= 1e-3f;
        done = (cl == FLT_MAX - 1e-3f) || (cl > 0.0f && B.b2 <= cl * cl);
    }

    if (!done) {
        for (int R = 2; R <= 2 * gs; R++) {
            int zlo = max(cz - R, 0), zhi = min(cz + R, gs - 1);
            for (int z = zlo; z <= zhi; z++) {
                bool zedge = (z == cz - R) || (z == cz + R);
                int ylo = max(cy - R, 0), yhi = min(cy + R, gs - 1);
                for (int y = ylo; y <= yhi; y++) {
                    bool yedge = (y == cy - R) || (y == cy + R);
                    int rowbase = (z * gs + y) * gs;
                    if (zedge || yedge) {
                        int xlo = max(cx - R, 0), xhi = min(cx + R, gs - 1);
                        int st = __ldg(&g_off[ob + rowbase + xlo]);
                        int en = __ldg(&g_off[ob + rowbase + xhi + 1]);
                        scan_range(st, en, sb, qx, qy, qz, B);
                    } else {
                        int xm = cx - R;
                        if (xm >= 0) scan_cell(rowbase + xm, ob, sb, qx, qy, qz, B);
                        int xp = cx + R;
                        if (xp < gs) scan_cell(rowbase + xp, ob, sb, qx, qy, qz, B);
                    }
                }
            }
            float cl = FLT_MAX;
            if (cx - R > 0)      cl = fminf(cl, qx - (bx0 + (cx - R) * csx));
            if (cx + R < gs - 1) cl = fminf(cl, (bx0 + (cx + R + 1) * csx) - qx);
            if (cy - R > 0)      cl = fminf(cl, qy - (by0 + (cy - R) * csy));
            if (cy + R < gs - 1) cl = fminf(cl, (by0 + (cy + R + 1) * csy) - qy);
            if (cz - R > 0)      cl = fminf(cl, qz - (bz0 + (cz - R) * csz));
            if (cz + R < gs - 1) cl = fminf(cl, (bz0 + (cz + R + 1) * csz) - qz);
            if (cl == FLT_MAX) break;             // whole grid scanned
            cl -= 1e-3f;                          // fp safety slack
            if (cl > 0.0f && B.b2 <= cl * cl) break;
        }
    }

    float w0 = 1.0f / (sqrtf(B.b0) + 1e-8f);
    float w1 = 1.0f / (sqrtf(B.b1) + 1e-8f);
    float w2 = 1.0f / (sqrtf(B.b2) + 1e-8f);
    float inv = 1.0f / (w0 + w1 + w2);

    size_t o = ((size_t)L * BATCH * NP + (size_t)b * NP + i) * 3;
    g_idx[o] = B.i0; g_idx[o + 1] = B.i1; g_idx[o + 2] = B.i2;
    g_w[o] = w0 * inv; g_w[o + 1] = w1 * inv; g_w[o + 2] = w2 * inv;
}

// ---------------- fused epilogue A: interp -> stats + write-through ----------
__global__ __launch_bounds__(MAXC) void statsA_all(EpiParams ep)
{
    const int L   = blockIdx.z;
    const int b   = blockIdx.y;
    const int blk = blockIdx.x;             // PB chunks
    const int c   = threadIdx.x;
    const int C   = ep.C[L];
    if (c >= C) return;
    const int pn  = NP / PB;                // 128

    const float* base = ep.vf[L] + (size_t)b * ep.Nv[L] * C;
    float* outp = ep.outp[L];
    float s = 0.f, q = 0.f;
    int p0 = blk * pn;
    for (int k = 0; k < pn; k++) {
        int i = p0 + k;                     // sorted position
        int p = g_pid[b * NP + i];          // original point index
        size_t o = ((size_t)L * BATCH * NP + (size_t)b * NP + i) * 3;
        int   i0 = g_idx[o], i1 = g_idx[o + 1], i2 = g_idx[o + 2];
        float w0 = g_w[o],   w1 = g_w[o + 1],   w2 = g_w[o + 2];
        float v = fmaf(w2, __ldg(&base[(size_t)i2 * C + c]),
                  fmaf(w1, __ldg(&base[(size_t)i1 * C + c]),
                       w0 * __ldg(&base[(size_t)i0 * C + c])));
        s += v;
        q = fmaf(v, v, q);
        outp[((size_t)b * NP + p) * C + c] = v;   // unnormalized write-through
    }
    size_t po = (((size_t)L * BATCH + b) * PB + blk) * MAXC + c;
    g_psum[po] = s;
    g_psqs[po] = q;
}

// ---------------- fused epilogue F: parallel finalize -------------------------
__global__ void statsF_all(EpiParams ep)
{
    __shared__ float ss[8][32], sq[8][32];
    const int L = blockIdx.z, b = blockIdx.y;
    const int tx = threadIdx.x, ty = threadIdx.y;
    const int c = blockIdx.x * 32 + tx;
    const int C = ep.C[L];

    float s = 0.f, q = 0.f;
    if (c < C) {
        size_t base = ((size_t)L * BATCH + b) * PB * MAXC + c;
        for (int k = ty; k < PB; k += 8) {
            s += g_psum[base + (size_t)k * MAXC];
            q += g_psqs[base + (size_t)k * MAXC];
        }
    }
    ss[ty][tx] = s; sq[ty][tx] = q;
    __syncthreads();
    if (ty == 0 && c < C) {
        #pragma unroll
        for (int r = 1; r < 8; r++) { s += ss[r][tx]; q += sq[r][tx]; }
        float m   = s * (1.0f / NP);
        float var = q * (1.0f / NP) - m * m;      // biased var, matches jnp.var
        size_t mo = ((size_t)L * BATCH + b) * MAXC + c;
        g_mu[mo]   = m;
        g_rstd[mo] = rsqrtf(var + 1e-5f);
    }
}

// ---------------- epilogue B: linear vectorized normalize in place ------------
__global__ __launch_bounds__(256) void normB_lin(EpiParams ep)
{
    const int L = blockIdx.z, b = blockIdx.y;
    const int C = ep.C[L];
    const int n4 = NP * C / 4;
    int i = blockIdx.x * 256 + threadIdx.x;
    if (i >= n4) return;

    int c4 = (i * 4) % C;                 // C % 4 == 0 -> 4 consecutive channels
    size_t mo = ((size_t)L * BATCH + b) * MAXC + c4;
    const float* gam = ep.gamma[L] + c4;
    const float* bet = ep.beta[L] + c4;

    float4* op = (float4*)(ep.outp[L] + (size_t)b * NP * C);
    float4 v = op[i];
    v.x = fmaf(gam[0] * g_rstd[mo + 0], v.x - g_mu[mo + 0], bet[0]);
    v.y = fmaf(gam[1] * g_rstd[mo + 1], v.y - g_mu[mo + 1], bet[1]);
    v.z = fmaf(gam[2] * g_rstd[mo + 2], v.z - g_mu[mo + 2], bet[2]);
    v.w = fmaf(gam[3] * g_rstd[mo + 3], v.w - g_mu[mo + 3], bet[3]);
    op[i] = v;
}

// ---------------- launch ------------------------------------------------------
// R12-validated grid sizes (best empirical operating point).
static inline int gs_for(int nv) {
    if (nv >= 32768) return 24;
    if (nv >= 4096)  return 16;
    return 8;
}

extern "C" void kernel_launch(void* const* d_in, const int* in_sizes, int n_in,
                              void* d_out, int out_size)
{
    const float* pt  = (const float*)d_in[0];
    float*       out = (float*)d_out;

    int nv[NLEV], cs[NLEV];
    for (int L = 0; L < NLEV; L++) {
        nv[L] = in_sizes[1 + 4 * L] / (BATCH * 3);
        cs[L] = in_sizes[2 + 4 * L] / (BATCH * nv[L]);
    }

    GridParams gp;
    ScanParams sp;
    int cbase = 0, svb = 0, maxnv = 0, nchunks = 0;
    // voxel slots 0..7, then point slots 8..9
    for (int s = 0; s < NSLOTT; s++) {
        int L = s >> 1, b = s & 1;
        if (s < NSLOTV) {
            gp.vc[s] = (const float*)d_in[1 + 4 * L] + (size_t)b * nv[L] * 3;
            gp.nv[s] = nv[L];
            gp.gs[s] = gs_for(nv[L]);
        } else {
            int pb = s - NSLOTV;
            gp.vc[s] = pt + (size_t)pb * NP * 3;
            gp.nv[s] = NP;
            gp.gs[s] = 32;
        }
        gp.cellbase[s] = cbase;
        gp.offbase[s]  = cbase + s;        // +1 sentinel per earlier slot
        gp.svbase[s]   = svb;
        sp.cstart[s]   = nchunks;
        int ncell = gp.gs[s] * gp.gs[s] * gp.gs[s];
        int ncell_pad = (ncell + CHUNK - 1) / CHUNK * CHUNK;  // pad to CHUNK
        cbase   += ncell_pad;
        svb     += gp.nv[s];
        nchunks += ncell_pad / CHUNK;
        if (gp.nv[s] > maxnv) maxnv = gp.nv[s];
    }
    sp.cstart[NSLOTT] = nchunks;
    int totcells = cbase;
    int nvblocks = (maxnv + 255) / 256;

    EpiParams ep;
    size_t off = 0;
    int maxC = 0;
    for (int L = 0; L < NLEV; L++) {
        ep.vf[L]    = (const float*)d_in[2 + 4 * L];
        ep.gamma[L] = (const float*)d_in[3 + 4 * L];
        ep.beta[L]  = (const float*)d_in[4 + 4 * L];
        ep.outp[L]  = out + off;
        ep.C[L]     = cs[L];
        ep.Nv[L]    = nv[L];
        off += (size_t)BATCH * NP * cs[L];
        if (cs[L] > maxC) maxC = cs[L];
    }

    init_kernel<<<(totcells + 255) / 256, 256>>>(totcells);
    bbox_kernel<<<dim3(nvblocks, NSLOTT), 256>>>(gp);
    count_kernel<<<dim3(nvblocks, NSLOTT), 256>>>(gp);
    scan1_kernel<<<nchunks, CHUNK>>>(gp, sp);
    scan2_kernel<<<1, NSLOTT * 32>>>(gp, sp);
    scan3_kernel<<<nchunks, CHUNK>>>(gp, sp);
    scatter_kernel<<<dim3(nvblocks, NSLOTT), 256>>>(gp);
    query_kernel<<<dim3(BATCH * NP / 256, NLEV), 256>>>(gp);

    statsA_all<<<dim3(PB, BATCH, NLEV), MAXC>>>(ep);
    statsF_all<<<dim3(MAXC / 32, BATCH, NLEV), dim3(32, 8)>>>(ep);
    int n4blocks = (NP * maxC / 4 + 255) / 256;
    normB_lin<<<dim3(n4blocks, BATCH, NLEV), 256>>>(ep);

    (void)n_in; (void)out_size;
}

// round 16
// speedup vs baseline: 1.2249x; 1.2249x over previous
#include <cuda_runtime.h>
#include <math.h>
#include <float.h>

#define BATCH 2
#define NP    32768
#define NLEV  4
#define NSLOTV 8           // (level, batch) voxel slots
#define NSLOTT 10          // + 2 point slots (one per batch)
#define PB    256          // stats partial chunks per batch
#define MAXC  256
#define CHUNK 512          // cells per scan chunk
#define MAXCHUNK 320

// ---------------- static device scratch (no allocations allowed) ------------
__device__ unsigned g_bb  [NSLOTT * 6];     // encoded bbox: min x,y,z / max x,y,z
__device__ int      g_cnt [150000];
__device__ int      g_off [150016];         // +1 sentinel per slot
__device__ int      g_fill[150000];
__device__ int      g_bsum[MAXCHUNK];
__device__ int      g_boff[MAXCHUNK];
__device__ float4   g_svox[184320];         // binned {x,y,z, idx-bits}
__device__ int      g_pid [BATCH * NP];     // sorted position -> original point idx
__device__ int      g_idx [NLEV * BATCH * NP * 3];   // indexed by SORTED position
__device__ float    g_w   [NLEV * BATCH * NP * 3];   // indexed by SORTED position
__device__ float    g_psum[NLEV * BATCH * PB * MAXC];
__device__ float    g_psqs[NLEV * BATCH * PB * MAXC];
__device__ float    g_mu  [NLEV * BATCH * MAXC];
__device__ float    g_rstd[NLEV * BATCH * MAXC];

struct GridParams {
    const float* vc[NSLOTT];
    int nv[NSLOTT];
    int gs[NSLOTT];
    int cellbase[NSLOTT];
    int offbase[NSLOTT];
    int svbase[NSLOTT];
};
struct ScanParams { int cstart[NSLOTT + 1]; };  // chunk-index boundaries per slot
struct EpiParams {
    const float* vf[NLEV];
    const float* gamma[NLEV];
    const float* beta[NLEV];
    float* outp[NLEV];
    int C[NLEV];
    int Nv[NLEV];
};

// order-preserving float <-> uint for atomicMin/Max
__device__ __forceinline__ unsigned fenc(float f) {
    unsigned u = __float_as_uint(f);
    return (u & 0x80000000u) ? ~u : (u | 0x80000000u);
}
__device__ __forceinline__ float fdec(unsigned u) {
    unsigned v = (u & 0x80000000u) ? (u & 0x7FFFFFFFu) : ~u;
    return __uint_as_float(v);
}
__device__ __forceinline__ int clampi(int v, int lo, int hi) {
    return v < lo ? lo : (v > hi ? hi : v);
}
__device__ __forceinline__ int chunk_slot(int ch, const ScanParams& sp) {
    int s = 0;
    #pragma unroll
    for (int i = 1; i < NSLOTT; i++) if (ch >= sp.cstart[i]) s = i;
    return s;
}

// Morton (Z-order) interleave
__device__ __forceinline__ unsigned part1by2(unsigned v) {
    v &= 0x3FF;
    v = (v | (v << 16)) & 0x030000FF;
    v = (v | (v <<  8)) & 0x0300F00F;
    v = (v | (v <<  4)) & 0x030C30C3;
    v = (v | (v <<  2)) & 0x09249249;
    return v;
}
// row-major for voxel slots (row-merged scans), Morton for point slots
__device__ __forceinline__ int cell_index(int s, int gs, int cx, int cy, int cz) {
    if (s < NSLOTV) return (cz * gs + cy) * gs + cx;
    return (int)(part1by2((unsigned)cx) | (part1by2((unsigned)cy) << 1)
               | (part1by2((unsigned)cz) << 2));
}

// ---------------- init ------------------------------------------------------
__global__ void init_kernel(int totcells) {
    int i = blockIdx.x * blockDim.x + threadIdx.x;
    if (i < totcells) { g_cnt[i] = 0; g_fill[i] = 0; }
    if (i < NSLOTT * 6) g_bb[i] = (i % 6 < 3) ? 0xFFFFFFFFu : 0u;
}

// ---------------- per-slot bbox ---------------------------------------------
__global__ void bbox_kernel(GridParams gp) {
    int s = blockIdx.y;
    int nv = gp.nv[s];
    int i = blockIdx.x * 256 + threadIdx.x;
    float x = FLT_MAX, y = FLT_MAX, z = FLT_MAX;
    float X = -FLT_MAX, Y = -FLT_MAX, Z = -FLT_MAX;
    if (i < nv) {
        const float* v = gp.vc[s] + (size_t)i * 3;
        x = X = v[0]; y = Y = v[1]; z = Z = v[2];
    }
    #pragma unroll
    for (int d = 16; d; d >>= 1) {
        x = fminf(x, __shfl_xor_sync(0xFFFFFFFFu, x, d));
        y = fminf(y, __shfl_xor_sync(0xFFFFFFFFu, y, d));
        z = fminf(z, __shfl_xor_sync(0xFFFFFFFFu, z, d));
        X = fmaxf(X, __shfl_xor_sync(0xFFFFFFFFu, X, d));
        Y = fmaxf(Y, __shfl_xor_sync(0xFFFFFFFFu, Y, d));
        Z = fmaxf(Z, __shfl_xor_sync(0xFFFFFFFFu, Z, d));
    }
    if ((threadIdx.x & 31) == 0) {
        atomicMin(&g_bb[s * 6 + 0], fenc(x));
        atomicMin(&g_bb[s * 6 + 1], fenc(y));
        atomicMin(&g_bb[s * 6 + 2], fenc(z));
        atomicMax(&g_bb[s * 6 + 3], fenc(X));
        atomicMax(&g_bb[s * 6 + 4], fenc(Y));
        atomicMax(&g_bb[s * 6 + 5], fenc(Z));
    }
}

// identical cell computation used by count / scatter / query
__device__ __forceinline__ void load_grid(int s, int gs,
    float& bx0, float& by0, float& bz0, float& sx, float& sy, float& sz) {
    bx0 = fdec(g_bb[s * 6 + 0]); by0 = fdec(g_bb[s * 6 + 1]); bz0 = fdec(g_bb[s * 6 + 2]);
    float bx1 = fdec(g_bb[s * 6 + 3]), by1 = fdec(g_bb[s * 6 + 4]), bz1 = fdec(g_bb[s * 6 + 5]);
    sx = gs / fmaxf(bx1 - bx0, 1e-9f);
    sy = gs / fmaxf(by1 - by0, 1e-9f);
    sz = gs / fmaxf(bz1 - bz0, 1e-9f);
}

// ---------------- count -----------------------------------------------------
__global__ void count_kernel(GridParams gp) {
    int s = blockIdx.y;
    int nv = gp.nv[s];
    int i = blockIdx.x * 256 + threadIdx.x;
    if (i >= nv) return;
    int gs = gp.gs[s];
    float bx0, by0, bz0, sx, sy, sz;
    load_grid(s, gs, bx0, by0, bz0, sx, sy, sz);
    const float* v = gp.vc[s] + (size_t)i * 3;
    int cx = clampi((int)((v[0] - bx0) * sx), 0, gs - 1);
    int cy = clampi((int)((v[1] - by0) * sy), 0, gs - 1);
    int cz = clampi((int)((v[2] - bz0) * sz), 0, gs - 1);
    atomicAdd(&g_cnt[gp.cellbase[s] + cell_index(s, gs, cx, cy, cz)], 1);
}

// ---------------- 3-phase scan (cell regions padded to CHUNK multiples) ------
__global__ __launch_bounds__(CHUNK) void scan1_kernel(GridParams gp, ScanParams sp) {
    __shared__ int ws[16];
    const int ch = blockIdx.x, t = threadIdx.x;
    const int s = chunk_slot(ch, sp);
    const int local = (ch - sp.cstart[s]) * CHUNK + t;
    const int lane = t & 31, wid = t >> 5;

    int v = g_cnt[gp.cellbase[s] + local];
    int sv = v;
    #pragma unroll
    for (int d = 1; d < 32; d <<= 1) {
        int o = __shfl_up_sync(0xFFFFFFFFu, sv, d);
        if (lane >= d) sv += o;
    }
    if (lane == 31) ws[wid] = sv;
    __syncthreads();
    if (wid == 0) {
        int w = (lane < 16) ? ws[lane] : 0;
        #pragma unroll
        for (int d = 1; d < 16; d <<= 1) {
            int o = __shfl_up_sync(0xFFFFFFFFu, w, d);
            if (lane >= d) w += o;
        }
        if (lane < 16) ws[lane] = w;
    }
    __syncthreads();
    int excl = sv - v + (wid ? ws[wid - 1] : 0);
    g_off[gp.offbase[s] + local] = excl;
    if (t == CHUNK - 1) g_bsum[ch] = excl + v;
}

__global__ void scan2_kernel(GridParams gp, ScanParams sp) {
    const int w = threadIdx.x >> 5;       // slot
    const int lane = threadIdx.x & 31;
    const int c0 = sp.cstart[w], c1 = sp.cstart[w + 1];
    int running = 0;
    for (int base = c0; base < c1; base += 32) {
        int i = base + lane;
        int v = (i < c1) ? g_bsum[i] : 0;
        int sv = v;
        #pragma unroll
        for (int d = 1; d < 32; d <<= 1) {
            int o = __shfl_up_sync(0xFFFFFFFFu, sv, d);
            if (lane >= d) sv += o;
        }
        if (i < c1) g_boff[i] = running + sv - v;
        running += __shfl_sync(0xFFFFFFFFu, sv, 31);
    }
    if (lane == 0) {
        int n = gp.gs[w] * gp.gs[w] * gp.gs[w];
        if (n % CHUNK == 0) g_off[gp.offbase[w] + n] = running;
    }
}

__global__ __launch_bounds__(CHUNK) void scan3_kernel(GridParams gp, ScanParams sp) {
    const int ch = blockIdx.x, t = threadIdx.x;
    const int s = chunk_slot(ch, sp);
    const int local = (ch - sp.cstart[s]) * CHUNK + t;
    g_off[gp.offbase[s] + local] += g_boff[ch];
}

// ---------------- scatter (also spatially sorts the points) ------------------
__global__ void scatter_kernel(GridParams gp) {
    int s = blockIdx.y;
    int nv = gp.nv[s];
    int i = blockIdx.x * 256 + threadIdx.x;
    if (i >= nv) return;
    int gs = gp.gs[s];
    float bx0, by0, bz0, sx, sy, sz;
    load_grid(s, gs, bx0, by0, bz0, sx, sy, sz);
    const float* v = gp.vc[s] + (size_t)i * 3;
    float x = v[0], y = v[1], z = v[2];
    int cx = clampi((int)((x - bx0) * sx), 0, gs - 1);
    int cy = clampi((int)((y - by0) * sy), 0, gs - 1);
    int cz = clampi((int)((z - bz0) * sz), 0, gs - 1);
    int cell = cell_index(s, gs, cx, cy, cz);
    int pos = g_off[gp.offbase[s] + cell] + atomicAdd(&g_fill[gp.cellbase[s] + cell], 1);
    g_svox[gp.svbase[s] + pos] = make_float4(x, y, z, __int_as_float(i));
}

// ---------------- query: exact 3-NN (R12-validated inner loop) ----------------
__device__ __forceinline__ void scan_range(int st, int en, int sb,
    float qx, float qy, float qz,
    float& b0, float& b1, float& b2, int& i0, int& i1, int& i2)
{
    for (int j = st; j < en; j++) {
        float4 v = __ldg(&g_svox[sb + j]);
        float dx = qx - v.x, dy = qy - v.y, dz = qz - v.z;
        float d2 = fmaf(dx, dx, fmaf(dy, dy, dz * dz));
        if (d2 < b2) {
            int idx = __float_as_int(v.w);
            if (d2 < b1) {
                b2 = b1; i2 = i1;
                if (d2 < b0) { b1 = b0; i1 = i0; b0 = d2; i0 = idx; }
                else         { b1 = d2; i1 = idx; }
            } else { b2 = d2; i2 = idx; }
        }
    }
}
__device__ __forceinline__ void scan_cell(int cell, int ob, int sb,
    float qx, float qy, float qz,
    float& b0, float& b1, float& b2, int& i0, int& i1, int& i2)
{
    int st = __ldg(&g_off[ob + cell]), en = __ldg(&g_off[ob + cell + 1]);
    scan_range(st, en, sb, qx, qy, qz, b0, b1, b2, i0, i1, i2);
}

// One thread = one (batch, point, LEVEL); points in Morton-sorted order.
__global__ __launch_bounds__(256) void query_kernel(GridParams gp)
{
    int gid = blockIdx.x * 256 + threadIdx.x;   // over BATCH*NP sorted points
    int L  = blockIdx.y;
    int b  = gid >> 15;
    int i  = gid & (NP - 1);

    float4 pv = __ldg(&g_svox[gp.svbase[NSLOTV + b] + i]);
    float qx = pv.x, qy = pv.y, qz = pv.z;

    if (L == 0) g_pid[b * NP + i] = __float_as_int(pv.w);

    const int s = L * 2 + b;
    int gs = gp.gs[s];
    float bx0, by0, bz0, sx, sy, sz;
    load_grid(s, gs, bx0, by0, bz0, sx, sy, sz);
    float csx = 1.0f / sx, csy = 1.0f / sy, csz = 1.0f / sz;

    int cx = clampi((int)((qx - bx0) * sx), 0, gs - 1);
    int cy = clampi((int)((qy - by0) * sy), 0, gs - 1);
    int cz = clampi((int)((qz - bz0) * sz), 0, gs - 1);

    const int ob = gp.offbase[s];
    const int sb = gp.svbase[s];

    float b0 = FLT_MAX, b1 = FLT_MAX, b2 = FLT_MAX;
    int i0 = 0, i1 = 0, i2 = 0;

    // ---- fast path: clamped 3x3x3 block, row-merged ----
    {
        int zlo = max(cz - 1, 0), zhi = min(cz + 1, gs - 1);
        int ylo = max(cy - 1, 0), yhi = min(cy + 1, gs - 1);
        int xlo = max(cx - 1, 0), xhi = min(cx + 1, gs - 1);
        for (int z = zlo; z <= zhi; z++)
            for (int y = ylo; y <= yhi; y++) {
                int rb = (z * gs + y) * gs;
                int st = __ldg(&g_off[ob + rb + xlo]);
                int en = __ldg(&g_off[ob + rb + xhi + 1]);
                scan_range(st, en, sb, qx, qy, qz, b0, b1, b2, i0, i1, i2);
            }
    }
    // clearance of the R=1 box
    bool done;
    {
        float cl = FLT_MAX;
        if (cx - 1 > 0)      cl = fminf(cl, qx - (bx0 + (cx - 1) * csx));
        if (cx + 1 < gs - 1) cl = fminf(cl, (bx0 + (cx + 2) * csx) - qx);
        if (cy - 1 > 0)      cl = fminf(cl, qy - (by0 + (cy - 1) * csy));
        if (cy + 1 < gs - 1) cl = fminf(cl, (by0 + (cy + 2) * csy) - qy);
        if (cz - 1 > 0)      cl = fminf(cl, qz - (bz0 + (cz - 1) * csz));
        if (cz + 1 < gs - 1) cl = fminf(cl, (bz0 + (cz + 2) * csz) - qz);
        cl -= 1e-3f;
        done = (cl == FLT_MAX - 1e-3f) || (cl > 0.0f && b2 <= cl * cl);
    }

    if (!done) {
        for (int R = 2; R <= 2 * gs; R++) {
            int zlo = max(cz - R, 0), zhi = min(cz + R, gs - 1);
            for (int z = zlo; z <= zhi; z++) {
                bool zedge = (z == cz - R) || (z == cz + R);
                int ylo = max(cy - R, 0), yhi = min(cy + R, gs - 1);
                for (int y = ylo; y <= yhi; y++) {
                    bool yedge = (y == cy - R) || (y == cy + R);
                    int rowbase = (z * gs + y) * gs;
                    if (zedge || yedge) {
                        int xlo = max(cx - R, 0), xhi = min(cx + R, gs - 1);
                        int st = __ldg(&g_off[ob + rowbase + xlo]);
                        int en = __ldg(&g_off[ob + rowbase + xhi + 1]);
                        scan_range(st, en, sb, qx, qy, qz, b0, b1, b2, i0, i1, i2);
                    } else {
                        int xm = cx - R;
                        if (xm >= 0) scan_cell(rowbase + xm, ob, sb, qx, qy, qz, b0, b1, b2, i0, i1, i2);
                        int xp = cx + R;
                        if (xp < gs) scan_cell(rowbase + xp, ob, sb, qx, qy, qz, b0, b1, b2, i0, i1, i2);
                    }
                }
            }
            float cl = FLT_MAX;
            if (cx - R > 0)      cl = fminf(cl, qx - (bx0 + (cx - R) * csx));
            if (cx + R < gs - 1) cl = fminf(cl, (bx0 + (cx + R + 1) * csx) - qx);
            if (cy - R > 0)      cl = fminf(cl, qy - (by0 + (cy - R) * csy));
            if (cy + R < gs - 1) cl = fminf(cl, (by0 + (cy + R + 1) * csy) - qy);
            if (cz - R > 0)      cl = fminf(cl, qz - (bz0 + (cz - R) * csz));
            if (cz + R < gs - 1) cl = fminf(cl, (bz0 + (cz + R + 1) * csz) - qz);
            if (cl == FLT_MAX) break;             // whole grid scanned
            cl -= 1e-3f;                          // fp safety slack
            if (cl > 0.0f && b2 <= cl * cl) break;
        }
    }

    float w0 = 1.0f / (sqrtf(b0) + 1e-8f);
    float w1 = 1.0f / (sqrtf(b1) + 1e-8f);
    float w2 = 1.0f / (sqrtf(b2) + 1e-8f);
    float inv = 1.0f / (w0 + w1 + w2);

    // write at SORTED position i (coalesced; epilogue walks sorted order)
    size_t o = ((size_t)L * BATCH * NP + (size_t)b * NP + i) * 3;
    g_idx[o] = i0; g_idx[o + 1] = i1; g_idx[o + 2] = i2;
    g_w[o] = w0 * inv; g_w[o + 1] = w1 * inv; g_w[o + 2] = w2 * inv;
}

// ---------------- fused epilogue A: float4-vectorized interp + stats ---------
// Thread = (channel-quad ci, point-slice ps). Each thread gathers float4 rows
// (4x fewer load instructions than scalar); idx/weight loads are per-point
// broadcast across the C4 threads of a slice. Slice partials reduced in smem.
__global__ __launch_bounds__(256) void statsA_all(EpiParams ep)
{
    __shared__ float4 ss4[256], sq4[256];
    const int L   = blockIdx.z;
    const int b   = blockIdx.y;
    const int blk = blockIdx.x;             // PB chunks
    const int tid = threadIdx.x;
    const int C   = ep.C[L];
    const int C4  = C >> 2;
    const int PS  = 256 / C4;               // point slices per block
    const int ci  = tid % C4;
    const int ps  = tid / C4;
    const int pn  = NP / PB;                // 128

    const float* base = ep.vf[L] + (size_t)b * ep.Nv[L] * C;
    float* outp = ep.outp[L];
    float4 s = make_float4(0.f, 0.f, 0.f, 0.f);
    float4 q = make_float4(0.f, 0.f, 0.f, 0.f);

    if (ps < PS) {
        int p0 = blk * pn;
        for (int k = ps; k < pn; k += PS) {
            int i = p0 + k;                 // sorted position
            int p = g_pid[b * NP + i];      // original point index
            size_t o = ((size_t)L * BATCH * NP + (size_t)b * NP + i) * 3;
            int   i0 = g_idx[o], i1 = g_idx[o + 1], i2 = g_idx[o + 2];
            float w0 = g_w[o],   w1 = g_w[o + 1],   w2 = g_w[o + 2];
            float4 v0 = __ldg((const float4*)(base + (size_t)i0 * C) + ci);
            float4 v1 = __ldg((const float4*)(base + (size_t)i1 * C) + ci);
            float4 v2 = __ldg((const float4*)(base + (size_t)i2 * C) + ci);
            float4 v;
            v.x = fmaf(w2, v2.x, fmaf(w1, v1.x, w0 * v0.x));
            v.y = fmaf(w2, v2.y, fmaf(w1, v1.y, w0 * v0.y));
            v.z = fmaf(w2, v2.z, fmaf(w1, v1.z, w0 * v0.z));
            v.w = fmaf(w2, v2.w, fmaf(w1, v1.w, w0 * v0.w));
            s.x += v.x; s.y += v.y; s.z += v.z; s.w += v.w;
            q.x = fmaf(v.x, v.x, q.x); q.y = fmaf(v.y, v.y, q.y);
            q.z = fmaf(v.z, v.z, q.z); q.w = fmaf(v.w, v.w, q.w);
            ((float4*)(outp + ((size_t)b * NP + p) * C))[ci] = v;
        }
    }
    ss4[tid] = s; sq4[tid] = q;
    __syncthreads();
    if (ps == 0) {
        for (int r = 1; r < PS; r++) {
            float4 a = ss4[r * C4 + ci], c = sq4[r * C4 + ci];
            s.x += a.x; s.y += a.y; s.z += a.z; s.w += a.w;
            q.x += c.x; q.y += c.y; q.z += c.z; q.w += c.w;
        }
        size_t po = (((size_t)L * BATCH + b) * PB + blk) * MAXC + ci * 4;
        *(float4*)&g_psum[po] = s;
        *(float4*)&g_psqs[po] = q;
    }
}

// ---------------- fused epilogue F: parallel finalize -------------------------
__global__ void statsF_all(EpiParams ep)
{
    __shared__ float ss[8][32], sq[8][32];
    const int L = blockIdx.z, b = blockIdx.y;
    const int tx = threadIdx.x, ty = threadIdx.y;
    const int c = blockIdx.x * 32 + tx;
    const int C = ep.C[L];

    float s = 0.f, q = 0.f;
    if (c < C) {
        size_t base = ((size_t)L * BATCH + b) * PB * MAXC + c;
        for (int k = ty; k < PB; k += 8) {
            s += g_psum[base + (size_t)k * MAXC];
            q += g_psqs[base + (size_t)k * MAXC];
        }
    }
    ss[ty][tx] = s; sq[ty][tx] = q;
    __syncthreads();
    if (ty == 0 && c < C) {
        #pragma unroll
        for (int r = 1; r < 8; r++) { s += ss[r][tx]; q += sq[r][tx]; }
        float m   = s * (1.0f / NP);
        float var = q * (1.0f / NP) - m * m;      // biased var, matches jnp.var
        size_t mo = ((size_t)L * BATCH + b) * MAXC + c;
        g_mu[mo]   = m;
        g_rstd[mo] = rsqrtf(var + 1e-5f);
    }
}

// ---------------- epilogue B: linear vectorized normalize in place ------------
__global__ __launch_bounds__(256) void normB_lin(EpiParams ep)
{
    const int L = blockIdx.z, b = blockIdx.y;
    const int C = ep.C[L];
    const int n4 = NP * C / 4;
    int i = blockIdx.x * 256 + threadIdx.x;
    if (i >= n4) return;

    int c4 = (i * 4) % C;                 // C % 4 == 0 -> 4 consecutive channels
    size_t mo = ((size_t)L * BATCH + b) * MAXC + c4;
    const float* gam = ep.gamma[L] + c4;
    const float* bet = ep.beta[L] + c4;

    float4* op = (float4*)(ep.outp[L] + (size_t)b * NP * C);
    float4 v = op[i];
    v.x = fmaf(gam[0] * g_rstd[mo + 0], v.x - g_mu[mo + 0], bet[0]);
    v.y = fmaf(gam[1] * g_rstd[mo + 1], v.y - g_mu[mo + 1], bet[1]);
    v.z = fmaf(gam[2] * g_rstd[mo + 2], v.z - g_mu[mo + 2], bet[2]);
    v.w = fmaf(gam[3] * g_rstd[mo + 3], v.w - g_mu[mo + 3], bet[3]);
    op[i] = v;
}

// ---------------- launch ------------------------------------------------------
// R12-validated grid sizes (best empirical operating point).
static inline int gs_for(int nv) {
    if (nv >= 32768) return 24;
    if (nv >= 4096)  return 16;
    return 8;
}

extern "C" void kernel_launch(void* const* d_in, const int* in_sizes, int n_in,
                              void* d_out, int out_size)
{
    const float* pt  = (const float*)d_in[0];
    float*       out = (float*)d_out;

    int nv[NLEV], cs[NLEV];
    for (int L = 0; L < NLEV; L++) {
        nv[L] = in_sizes[1 + 4 * L] / (BATCH * 3);
        cs[L] = in_sizes[2 + 4 * L] / (BATCH * nv[L]);
    }

    GridParams gp;
    ScanParams sp;
    int cbase = 0, svb = 0, maxnv = 0, nchunks = 0;
    // voxel slots 0..7, then point slots 8..9
    for (int s = 0; s < NSLOTT; s++) {
        int L = s >> 1, b = s & 1;
        if (s < NSLOTV) {
            gp.vc[s] = (const float*)d_in[1 + 4 * L] + (size_t)b * nv[L] * 3;
            gp.nv[s] = nv[L];
            gp.gs[s] = gs_for(nv[L]);
        } else {
            int pb = s - NSLOTV;
            gp.vc[s] = pt + (size_t)pb * NP * 3;
            gp.nv[s] = NP;
            gp.gs[s] = 32;
        }
        gp.cellbase[s] = cbase;
        gp.offbase[s]  = cbase + s;        // +1 sentinel per earlier slot
        gp.svbase[s]   = svb;
        sp.cstart[s]   = nchunks;
        int ncell = gp.gs[s] * gp.gs[s] * gp.gs[s];
        int ncell_pad = (ncell + CHUNK - 1) / CHUNK * CHUNK;  // pad to CHUNK
        cbase   += ncell_pad;
        svb     += gp.nv[s];
        nchunks += ncell_pad / CHUNK;
        if (gp.nv[s] > maxnv) maxnv = gp.nv[s];
    }
    sp.cstart[NSLOTT] = nchunks;
    int totcells = cbase;
    int nvblocks = (maxnv + 255) / 256;

    EpiParams ep;
    size_t off = 0;
    int maxC = 0;
    for (int L = 0; L < NLEV; L++) {
        ep.vf[L]    = (const float*)d_in[2 + 4 * L];
        ep.gamma[L] = (const float*)d_in[3 + 4 * L];
        ep.beta[L]  = (const float*)d_in[4 + 4 * L];
        ep.outp[L]  = out + off;
        ep.C[L]     = cs[L];
        ep.Nv[L]    = nv[L];
        off += (size_t)BATCH * NP * cs[L];
        if (cs[L] > maxC) maxC = cs[L];
    }

    init_kernel<<<(totcells + 255) / 256, 256>>>(totcells);
    bbox_kernel<<<dim3(nvblocks, NSLOTT), 256>>>(gp);
    count_kernel<<<dim3(nvblocks, NSLOTT), 256>>>(gp);
    scan1_kernel<<<nchunks, CHUNK>>>(gp, sp);
    scan2_kernel<<<1, NSLOTT * 32>>>(gp, sp);
    scan3_kernel<<<nchunks, CHUNK>>>(gp, sp);
    scatter_kernel<<<dim3(nvblocks, NSLOTT), 256>>>(gp);
    query_kernel<<<dim3(BATCH * NP / 256, NLEV), 256>>>(gp);

    statsA_all<<<dim3(PB, BATCH, NLEV), 256>>>(ep);
    statsF_all<<<dim3(MAXC / 32, BATCH, NLEV), dim3(32, 8)>>>(ep);
    int n4blocks = (NP * maxC / 4 + 255) / 256;
    normB_lin<<<dim3(n4blocks, BATCH, NLEV), 256>>>(ep);

    (void)n_in; (void)out_size;
}